// round 17
// baseline (speedup 1.0000x reference)
#include <cuda_runtime.h>

#define B_ 256
#define S_ 512
#define V_ 32000
#define D_ 100
#define H_ 75
#define HP_ 76    // g_embp row stride
#define KP_ 80    // padded state stride (76 used, 16B-aligned)
#define L_ 128
#define NTHR 320  // 10 warps: C=0..3, B=4..6, A=7..9 (A = highest wid = arbiter priority)
#define RING 8
#define EPOCHS (S_ / 4 + 2)   // 130: A epochs 0..127, B lags 4, C lags 8

// Precomputed emb @ W1^T + b1, stride 76. 32000*76*4 = 9.73 MB (L2-resident).
__device__ float g_embp[V_ * HP_];

// ---------------------------------------------------------------------------
// Kernel 1: embp[v][j] = sum_d emb[v][d] * W1[j][d] + b1[j]
// ---------------------------------------------------------------------------
__global__ __launch_bounds__(256) void embp_kernel(const float* __restrict__ emb,
                                                   const float* __restrict__ W1,
                                                   const float* __restrict__ b1) {
    __shared__ float w1s[H_ * D_];
    __shared__ float es[64 * D_];
    const int r0 = blockIdx.x * 64;

    for (int idx = threadIdx.x; idx < H_ * D_; idx += 256) w1s[idx] = W1[idx];
    for (int idx = threadIdx.x; idx < 64 * D_; idx += 256) es[idx] = emb[r0 * D_ + idx];
    __syncthreads();

    for (int o = threadIdx.x; o < 64 * H_; o += 256) {
        const int rr = o / H_;
        const int j  = o - rr * H_;
        const float* ep = es + rr * D_;
        const float* wp = w1s + j * D_;
        float4 a = {0.f, 0.f, 0.f, 0.f};
#pragma unroll
        for (int k = 0; k < D_ / 4; ++k) {
            float4 ev = *(const float4*)(ep + 4 * k);
            float4 wv = *(const float4*)(wp + 4 * k);
            a.x += ev.x * wv.x; a.y += ev.y * wv.y;
            a.z += ev.z * wv.z; a.w += ev.w * wv.w;
        }
        g_embp[(r0 + rr) * HP_ + j] = a.x + a.y + a.z + a.w + b1[j];
    }
}

// ---------------------------------------------------------------------------
// Packed fp32x2 helpers (sm_103a)
// ---------------------------------------------------------------------------
__device__ __forceinline__ unsigned long long pack2(float lo, float hi) {
    unsigned long long d;
    asm("mov.b64 %0, {%1, %2};" : "=l"(d) : "f"(lo), "f"(hi));
    return d;
}
__device__ __forceinline__ void fma2(unsigned long long& d, unsigned long long a,
                                     unsigned long long b) {
    asm("fma.rn.f32x2 %0, %1, %2, %0;" : "+l"(d) : "l"(a), "l"(b));
}
__device__ __forceinline__ float hsum4(unsigned long long a, unsigned long long b,
                                       unsigned long long c, unsigned long long d) {
    unsigned long long s0, s1;
    asm("add.rn.f32x2 %0, %1, %2;" : "=l"(s0) : "l"(a), "l"(b));
    asm("add.rn.f32x2 %0, %1, %2;" : "=l"(s1) : "l"(c), "l"(d));
    asm("add.rn.f32x2 %0, %1, %2;" : "=l"(s0) : "l"(s0), "l"(s1));
    float lo, hi;
    asm("mov.b64 {%0, %1}, %2;" : "=f"(lo), "=f"(hi) : "l"(s0));
    return lo + hi;
}
__device__ __forceinline__ float sigm(float z) {
    return __fdividef(1.0f, 1.0f + __expf(-z));
}
__device__ __forceinline__ void barA() {      // A-group barrier: warps 7-9 only
    asm volatile("bar.sync 1, 96;" ::: "memory");
}

// Full 76-float dot of smem vector (16B-aligned, zero-padded) against 38
// packed-f32x2 register weights. 4 accumulators -> dep chain depth ~10.
__device__ __forceinline__ float dot76(const float* __restrict__ v,
                                       const unsigned long long* __restrict__ w) {
    const ulonglong2* p = (const ulonglong2*)v;
    unsigned long long a0 = 0ull, a1 = 0ull, a2 = 0ull, a3 = 0ull;
#pragma unroll
    for (int i = 0; i < 19; ++i) {
        const ulonglong2 hv = p[i];               // broadcast LDS.128
        if (i & 1) { fma2(a2, w[2 * i], hv.x); fma2(a3, w[2 * i + 1], hv.y); }
        else       { fma2(a0, w[2 * i], hv.x); fma2(a1, w[2 * i + 1], hv.y); }
    }
    return hsum4(a0, a1, a2, a3);
}

// ---------------------------------------------------------------------------
// Kernel 2: decoupled-role recurrence with WARP-PRIORITY-AWARE role layout.
// B300 SMSP arbiter is highest-wid-first: the serial-critical A role now
// occupies the TOP warps (7-9) so it wins issue arbitration over the
// latency-tolerant B (4-6) and C (0-3) roles.
//   warps 7-9: A  h_t   = sigm(W2 . h_{t-1} + xp_t + b2)   -> hring[t&7]
//   warps 4-6: B  o_t   = sigm(Wo . h_t + bo)              -> oring[t&7]
//   warps 0-3: C  out_t = Wfc . o_t + bfc                  -> gmem
// Ring depth 8; B lags A by 4 steps, C lags B by 4; A-only named barrier per
// step; one __syncthreads per 4-step epoch (publishes A->B, B->C).
// ---------------------------------------------------------------------------
__global__ __launch_bounds__(NTHR, 2) void rnn_kernel(
    const int*   __restrict__ X,
    const float* __restrict__ W2, const float* __restrict__ b2,
    const float* __restrict__ Wo, const float* __restrict__ bo,
    const float* __restrict__ Wfc, const float* __restrict__ bfc,
    float* __restrict__ out)
{
    __shared__ __align__(16) float hring[RING][KP_];
    __shared__ __align__(16) float oring[RING][KP_];
    __shared__ int toks[S_];

    const int tid = threadIdx.x;
    const int row = blockIdx.x;

    const bool isC = tid < 128;                       // warps 0-3
    const bool isB = (tid >= 128) && (tid < 224);     // warps 4-6
    const bool isA = tid >= 224;                      // warps 7-9 (highest priority)
    const int  j   = isC ? tid : (isB ? tid - 128 : tid - 224);
    const int  nrows = isC ? L_ : H_;
    const bool vj  = j < nrows;

    // ---- init rings + tokens ----
    for (int i = tid; i < RING * KP_; i += NTHR) {
        ((float*)hring)[i] = 0.f; ((float*)oring)[i] = 0.f;
    }
    for (int i = tid; i < S_; i += NTHR) toks[i] = X[row * S_ + i];

    // ---- weights: one row per thread, packed k-pairs (38 x u64) ----
    const float* Wbase = isA ? W2 : (isB ? Wo : Wfc);
    unsigned long long w[38];
#pragma unroll
    for (int c = 0; c < 38; ++c) {
        const int k = 2 * c;
        float lo = 0.f, hi = 0.f;
        if (vj) {
            if (k     < H_) lo = Wbase[j * H_ + k];
            if (k + 1 < H_) hi = Wbase[j * H_ + k + 1];
        }
        w[c] = pack2(lo, hi);
    }
    float br = 0.f;
    if (vj) br = isA ? b2[j] : (isB ? bo[j] : bfc[j]);
    float* outp = out + ((size_t)row * S_) * L_ + j;   // used by C

    __syncthreads();

    // xp for epoch 0 (steps 0..3)
    float xq[4];
    if (isA && vj) {
#pragma unroll
        for (int s = 0; s < 4; ++s)
            xq[s] = g_embp[(size_t)toks[s] * HP_ + j];
    }

    for (int e = 0; e < EPOCHS; ++e) {
        const int te = 4 * e;

        if (isA) {
            // 4 recurrence steps; only A warps barrier between them.
#pragma unroll
            for (int s = 0; s < 4; ++s) {
                const int tA = te + s;
                if (vj && tA < S_) {
                    const float z = dot76(hring[(tA + RING - 1) & (RING - 1)], w)
                                    + xq[s] + br;
                    hring[tA & (RING - 1)][j] = sigm(z);
                }
                // prefetch next epoch's xp for this substep (overlaps chain)
                if (vj) {
                    const int tn = tA + 4;
                    xq[s] = (tn < S_) ? g_embp[(size_t)toks[tn] * HP_ + j] : 0.f;
                }
                barA();
            }
        } else if (isB) {
            // 4 trailing o-steps, no internal barriers (inputs stable this epoch)
#pragma unroll
            for (int s = 0; s < 4; ++s) {
                const int tB = te + s - 4;
                if (vj && tB >= 0 && tB < S_) {
                    const float z = dot76(hring[tB & (RING - 1)], w) + br;
                    oring[tB & (RING - 1)][j] = sigm(z);
                }
            }
        } else {
            // 4 trailing fc outputs, no internal barriers
#pragma unroll
            for (int s = 0; s < 4; ++s) {
                const int tC = te + s - 8;
                if (tC >= 0 && tC < S_) {
                    const float z = dot76(oring[tC & (RING - 1)], w) + br;
                    outp[(size_t)tC * L_] = z;
                }
            }
        }
        __syncthreads();   // publish A->B (h) and B->C (o) for next epoch
    }
}

// ---------------------------------------------------------------------------
extern "C" void kernel_launch(void* const* d_in, const int* in_sizes, int n_in,
                              void* d_out, int out_size) {
    const int*   X   = (const int*)d_in[0];
    const float* emb = (const float*)d_in[1];
    const float* W1  = (const float*)d_in[2];
    const float* b1  = (const float*)d_in[3];
    const float* W2  = (const float*)d_in[4];
    const float* b2  = (const float*)d_in[5];
    const float* Wo  = (const float*)d_in[6];
    const float* bo  = (const float*)d_in[7];
    const float* Wfc = (const float*)d_in[8];
    const float* bfc = (const float*)d_in[9];
    float* out = (float*)d_out;

    embp_kernel<<<V_ / 64, 256>>>(emb, W1, b1);
    rnn_kernel<<<B_, NTHR>>>(X, W2, b2, Wo, bo, Wfc, bfc, out);
}